// round 1
// baseline (speedup 1.0000x reference)
#include <cuda_runtime.h>
#include <cstdint>

#define NB   64      // B
#define NP   2048    // P
#define NL   512     // L
#define NDM  512     // D_MODEL
#define NH   8       // heads
#define NDK  64
#define SPLIT 8
#define ROWS_PER_BLK (NP/SPLIT)   // 256
#define TILE 16
#define NTILES (ROWS_PER_BLK/TILE) // 16

#define NEG_INF (__int_as_float(0xff800000))

// ------------------------- scratch (static device memory) -------------------------
__device__ float g_ug[NB*NH*NL];         // (u * lnkv_g) per (b,h,l)
__device__ float g_ugs[NB*NH];           // sum_l ug
__device__ float g_ub[NB*NH];            // sum_l u * lnkv_b
__device__ float g_scores[NB*NH*NP];     // raw scores
__device__ float g_pm[NB*SPLIT*NH];      // partial max
__device__ float g_pz[NB*SPLIT*NH];      // partial Z
__device__ float g_pt[NB*SPLIT*NH];      // partial T
__device__ float g_pa[NB*SPLIT*NH*NL];   // partial A (8 MB)
__device__ float g_Mx[NB*NH];            // final max
__device__ float g_invZ[NB*NH];          // 1/Z
__device__ float g_ctx[NB*NDM];          // attention context

// ------------------------- helpers -------------------------
__device__ __forceinline__ uint32_t s2u(const void* p) {
    return (uint32_t)__cvta_generic_to_shared(p);
}
__device__ __forceinline__ void cp_async16(uint32_t s, const void* g) {
    asm volatile("cp.async.cg.shared.global [%0], [%1], 16;\n" :: "r"(s), "l"(g));
}
#define CP_COMMIT() asm volatile("cp.async.commit_group;\n")
#define CP_WAIT1()  asm volatile("cp.async.wait_group 1;\n")
#define CP_WAIT0()  asm volatile("cp.async.wait_group 0;\n")

// =========================================================================
// Kernel 1: per batch b: lnq = LN(x_trafic[b]); Q = lnq @ W_q;
//           u[h,l] = sum_d W_k[l, h*64+d] * Q[h*64+d];
//           g_ug = u * lnkv_g; g_ugs = sum ug; g_ub = sum u*lnkv_b
// =========================================================================
__global__ void __launch_bounds__(512) k1_prep(
    const float* __restrict__ x_trafic,
    const float* __restrict__ W_q, const float* __restrict__ W_k,
    const float* __restrict__ lnq_g, const float* __restrict__ lnq_b,
    const float* __restrict__ lnkv_g, const float* __restrict__ lnkv_b)
{
    __shared__ float  lnq_s[NL];
    __shared__ float4 Q_s4[NL/4];
    __shared__ float4 part4[4*128];
    __shared__ float  red1[16], red2[16];
    __shared__ float  sc_mean, sc_r;
    __shared__ float  ugs_sm[NH], ub_sm[NH];

    const int t = threadIdx.x, b = blockIdx.x;
    const int lane = t & 31, wid = t >> 5;

    if (t < NH) { ugs_sm[t] = 0.f; ub_sm[t] = 0.f; }

    // LN stats of x_trafic row
    float v = x_trafic[b*NL + t];
    float s1 = v, s2v = v*v;
    #pragma unroll
    for (int o = 16; o > 0; o >>= 1) {
        s1  += __shfl_xor_sync(~0u, s1, o);
        s2v += __shfl_xor_sync(~0u, s2v, o);
    }
    if (lane == 0) { red1[wid] = s1; red2[wid] = s2v; }
    __syncthreads();
    if (t == 0) {
        float a = 0.f, c = 0.f;
        #pragma unroll
        for (int i = 0; i < 16; i++) { a += red1[i]; c += red2[i]; }
        float mean = a * (1.f/NL);
        float var  = c * (1.f/NL) - mean*mean;
        sc_mean = mean;
        sc_r = rsqrtf(var + 1e-5f);
    }
    __syncthreads();
    lnq_s[t] = (v - sc_mean) * sc_r * lnq_g[t] + lnq_b[t];
    __syncthreads();

    // Q = lnq @ W_q : 128 output-groups x 4 l-groups
    {
        const int og = t & 127, lg = t >> 7;
        const float4* Wq4 = (const float4*)W_q;
        float4 acc = {0,0,0,0};
        const int l0 = lg * 128;
        for (int l = l0; l < l0 + 128; l++) {
            float s = lnq_s[l];
            float4 w = Wq4[l*128 + og];
            acc.x += s*w.x; acc.y += s*w.y; acc.z += s*w.z; acc.w += s*w.w;
        }
        part4[lg*128 + og] = acc;
    }
    __syncthreads();
    if (t < 128) {
        float4 a = part4[t], b2 = part4[128+t], c = part4[256+t], d = part4[384+t];
        a.x += b2.x + c.x + d.x;
        a.y += b2.y + c.y + d.y;
        a.z += b2.z + c.z + d.z;
        a.w += b2.w + c.w + d.w;
        Q_s4[t] = a;
    }
    __syncthreads();

    // u[h,l]: warp wid handles rows l = wid + 16*it; lane covers 16 contiguous cols (head = lane/4)
    const float4* Wk4 = (const float4*)W_k;
    const int h = lane >> 2;
    float ugs_p = 0.f, ub_p = 0.f;
    for (int it = 0; it < 32; it++) {
        int l = wid + 16*it;
        float acc = 0.f;
        #pragma unroll
        for (int j = 0; j < 4; j++) {
            float4 w = Wk4[l*128 + lane*4 + j];
            float4 q = Q_s4[lane*4 + j];
            acc += w.x*q.x + w.y*q.y + w.z*q.z + w.w*q.w;
        }
        acc += __shfl_xor_sync(~0u, acc, 1);
        acc += __shfl_xor_sync(~0u, acc, 2);
        if ((lane & 3) == 0) {
            float ug = acc * lnkv_g[l];
            g_ug[(b*NH + h)*NL + l] = ug;
            ugs_p += ug;
            ub_p  += acc * lnkv_b[l];
        }
    }
    if ((lane & 3) == 0) {
        atomicAdd(&ugs_sm[h], ugs_p);
        atomicAdd(&ub_sm[h], ub_p);
    }
    __syncthreads();
    if (t < NH) {
        g_ugs[b*NH + t] = ugs_sm[t];
        g_ub [b*NH + t] = ub_sm[t];
    }
}

// =========================================================================
// Kernel 2: main fused pass over x_dynamic (single HBM read).
// Per block (split, b): 256 rows in tiles of 16.
//  phase3: warp-per-row LN stats + 8 head dots -> scores
//  phase4: online softmax update per head (warp 0)
//  phase5: col-distributed accumulation A[h][l] += e'*x
// =========================================================================
__global__ void __launch_bounds__(512) k2_main(const float* __restrict__ x_dyn)
{
    extern __shared__ float sm[];
    float* buf     = sm;                     // 2*16*512
    float* ug_s    = sm + 2*TILE*NL;         // 4096
    float* sc_s    = ug_s + NH*NL;           // 128
    float* ea_s    = sc_s + NH*TILE;         // 128
    float* scale_s = ea_s + NH*TILE;         // 8
    float* mrow_s  = scale_s + NH;           // 16
    float* rrow_s  = mrow_s + TILE;          // 16
    float* mrun_s  = rrow_s + TILE;          // 8
    float* zrun_s  = mrun_s + NH;            // 8
    float* trun_s  = zrun_s + NH;            // 8
    float* ugs_s   = trun_s + NH;            // 8
    float* ub_s    = ugs_s + NH;             // 8

    const int t = threadIdx.x;
    const int split = blockIdx.x, b = blockIdx.y;
    const int lane = t & 31, wid = t >> 5;

    // load ug tile for this b (4096 floats)
    {
        const float4* gug4 = (const float4*)(g_ug + (size_t)b*NH*NL);
        float4* ug4 = (float4*)ug_s;
        ug4[t]       = gug4[t];
        ug4[t + 512] = gug4[t + 512];
    }
    if (t < NH) {
        ugs_s[t] = g_ugs[b*NH + t];
        ub_s [t] = g_ub [b*NH + t];
        mrun_s[t] = NEG_INF; zrun_s[t] = 0.f; trun_s[t] = 0.f;
    }

    const float* xbase = x_dyn + ((size_t)b*NP + (size_t)split*ROWS_PER_BLK)*NL;

    // prefetch tile 0
    {
        uint32_t dst = s2u(buf);
        const float4* src = (const float4*)xbase;
        #pragma unroll
        for (int j = 0; j < 4; j++)
            cp_async16(dst + (uint32_t)(t + 512*j)*16u, src + t + 512*j);
        CP_COMMIT();
    }

    const int hg = t >> 7, cg = t & 127;
    const int h0 = 2*hg, h1 = 2*hg + 1;
    float4 A0 = {0,0,0,0}, A1 = {0,0,0,0};
    const float4* ug4s = (const float4*)ug_s;

    __syncthreads();

    #pragma unroll 1
    for (int tile = 0; tile < NTILES; tile++) {
        float* xb = buf + (tile & 1)*TILE*NL;
        if (tile + 1 < NTILES) {
            float* nb = buf + ((tile+1) & 1)*TILE*NL;
            uint32_t dst = s2u(nb);
            const float4* src = (const float4*)(xbase + (size_t)(tile+1)*TILE*NL);
            #pragma unroll
            for (int j = 0; j < 4; j++)
                cp_async16(dst + (uint32_t)(t + 512*j)*16u, src + t + 512*j);
            CP_COMMIT();
            CP_WAIT1();
        } else {
            CP_WAIT0();
        }
        __syncthreads();

        // ---- phase 3: warp wid processes row wid ----
        {
            const float4* xr = (const float4*)(xb + wid*NL);
            float dd[8];
            float sum, sq;
            {   // heads 0..3 + stats
                float4 s4 = {0,0,0,0}, q4 = {0,0,0,0};
                float4 dv0={0,0,0,0}, dv1={0,0,0,0}, dv2={0,0,0,0}, dv3={0,0,0,0};
                #pragma unroll
                for (int i = 0; i < 4; i++) {
                    float4 v = xr[lane + 32*i];
                    s4.x += v.x; s4.y += v.y; s4.z += v.z; s4.w += v.w;
                    q4.x += v.x*v.x; q4.y += v.y*v.y; q4.z += v.z*v.z; q4.w += v.w*v.w;
                    float4 u0 = ug4s[0*128 + lane + 32*i];
                    float4 u1 = ug4s[1*128 + lane + 32*i];
                    float4 u2 = ug4s[2*128 + lane + 32*i];
                    float4 u3 = ug4s[3*128 + lane + 32*i];
                    dv0.x += v.x*u0.x; dv0.y += v.y*u0.y; dv0.z += v.z*u0.z; dv0.w += v.w*u0.w;
                    dv1.x += v.x*u1.x; dv1.y += v.y*u1.y; dv1.z += v.z*u1.z; dv1.w += v.w*u1.w;
                    dv2.x += v.x*u2.x; dv2.y += v.y*u2.y; dv2.z += v.z*u2.z; dv2.w += v.w*u2.w;
                    dv3.x += v.x*u3.x; dv3.y += v.y*u3.y; dv3.z += v.z*u3.z; dv3.w += v.w*u3.w;
                }
                dd[0] = dv0.x+dv0.y+dv0.z+dv0.w;
                dd[1] = dv1.x+dv1.y+dv1.z+dv1.w;
                dd[2] = dv2.x+dv2.y+dv2.z+dv2.w;
                dd[3] = dv3.x+dv3.y+dv3.z+dv3.w;
                sum = s4.x+s4.y+s4.z+s4.w;
                sq  = q4.x+q4.y+q4.z+q4.w;
            }
            {   // heads 4..7
                float4 dv0={0,0,0,0}, dv1={0,0,0,0}, dv2={0,0,0,0}, dv3={0,0,0,0};
                #pragma unroll
                for (int i = 0; i < 4; i++) {
                    float4 v = xr[lane + 32*i];
                    float4 u0 = ug4s[4*128 + lane + 32*i];
                    float4 u1 = ug4s[5*128 + lane + 32*i];
                    float4 u2 = ug4s[6*128 + lane + 32*i];
                    float4 u3 = ug4s[7*128 + lane + 32*i];
                    dv0.x += v.x*u0.x; dv0.y += v.y*u0.y; dv0.z += v.z*u0.z; dv0.w += v.w*u0.w;
                    dv1.x += v.x*u1.x; dv1.y += v.y*u1.y; dv1.z += v.z*u1.z; dv1.w += v.w*u1.w;
                    dv2.x += v.x*u2.x; dv2.y += v.y*u2.y; dv2.z += v.z*u2.z; dv2.w += v.w*u2.w;
                    dv3.x += v.x*u3.x; dv3.y += v.y*u3.y; dv3.z += v.z*u3.z; dv3.w += v.w*u3.w;
                }
                dd[4] = dv0.x+dv0.y+dv0.z+dv0.w;
                dd[5] = dv1.x+dv1.y+dv1.z+dv1.w;
                dd[6] = dv2.x+dv2.y+dv2.z+dv2.w;
                dd[7] = dv3.x+dv3.y+dv3.z+dv3.w;
            }
            #pragma unroll
            for (int o = 16; o > 0; o >>= 1) {
                sum += __shfl_xor_sync(~0u, sum, o);
                sq  += __shfl_xor_sync(~0u, sq,  o);
                #pragma unroll
                for (int k = 0; k < 8; k++) dd[k] += __shfl_xor_sync(~0u, dd[k], o);
            }
            float mean = sum * (1.f/NL);
            float var  = sq  * (1.f/NL) - mean*mean;
            float r = rsqrtf(var + 1e-5f);
            if (lane == 0) { mrow_s[wid] = mean; rrow_s[wid] = r; }
            if (lane < NH) {
                float dsel = dd[0];
                #pragma unroll
                for (int k = 1; k < 8; k++) if (lane == k) dsel = dd[k];
                float s = (r * (dsel - mean * ugs_s[lane]) + ub_s[lane]) * 0.125f;
                sc_s[lane*TILE + wid] = s;
                g_scores[((size_t)(b*NH + lane))*NP + split*ROWS_PER_BLK + tile*TILE + wid] = s;
            }
        }
        __syncthreads();

        // ---- phase 4: online softmax update (threads 0..7, one per head) ----
        if (t < NH) {
            const int h = t;
            float mr = mrun_s[h];
            float tmax = NEG_INF;
            #pragma unroll
            for (int p = 0; p < TILE; p++) tmax = fmaxf(tmax, sc_s[h*TILE + p]);
            float mn = fmaxf(mr, tmax);
            float scale = __expf(mr - mn);
            float zadd = 0.f, tadd = 0.f;
            #pragma unroll
            for (int p = 0; p < TILE; p++) {
                float e  = __expf(sc_s[h*TILE + p] - mn);
                float ea = e * rrow_s[p];
                ea_s[h*TILE + p] = ea;
                zadd += e;
                tadd += ea * mrow_s[p];
            }
            zrun_s[h] = zrun_s[h]*scale + zadd;
            trun_s[h] = trun_s[h]*scale + tadd;
            mrun_s[h] = mn;
            scale_s[h] = scale;
        }
        __syncthreads();

        // ---- phase 5: accumulate A (thread owns 4 cols x 2 heads) ----
        {
            float sc0 = scale_s[h0], sc1 = scale_s[h1];
            A0.x *= sc0; A0.y *= sc0; A0.z *= sc0; A0.w *= sc0;
            A1.x *= sc1; A1.y *= sc1; A1.z *= sc1; A1.w *= sc1;
            const float4* xc = (const float4*)xb;
            #pragma unroll
            for (int p = 0; p < TILE; p++) {
                float4 v = xc[p*128 + cg];
                float e0 = ea_s[h0*TILE + p];
                float e1 = ea_s[h1*TILE + p];
                A0.x += e0*v.x; A0.y += e0*v.y; A0.z += e0*v.z; A0.w += e0*v.w;
                A1.x += e1*v.x; A1.y += e1*v.y; A1.z += e1*v.z; A1.w += e1*v.w;
            }
        }
        __syncthreads();
    }

    // epilogue: write partials
    {
        float* pa = g_pa + (size_t)(b*SPLIT + split)*NH*NL;
        ((float4*)(pa + h0*NL))[cg] = A0;
        ((float4*)(pa + h1*NL))[cg] = A1;
    }
    if (t < NH) {
        int idx = (b*SPLIT + split)*NH + t;
        g_pm[idx] = mrun_s[t];
        g_pz[idx] = zrun_s[t];
        g_pt[idx] = trun_s[t];
    }
}

// =========================================================================
// Kernel 3: combine split partials per (b,h); project through W_v -> ctx
// =========================================================================
__global__ void __launch_bounds__(256) k3_combine(
    const float* __restrict__ W_v,
    const float* __restrict__ lnkv_g, const float* __restrict__ lnkv_b)
{
    __shared__ float es[SPLIT];
    __shared__ float sT, sInvZ;
    __shared__ float cvec[NL];
    __shared__ float part[4*64];

    const int t = threadIdx.x;
    const int b = blockIdx.x >> 3, h = blockIdx.x & 7;

    if (t == 0) {
        float M = NEG_INF;
        #pragma unroll
        for (int i = 0; i < SPLIT; i++)
            M = fmaxf(M, g_pm[(b*SPLIT + i)*NH + h]);
        float Z = 0.f, T = 0.f;
        #pragma unroll
        for (int i = 0; i < SPLIT; i++) {
            int idx = (b*SPLIT + i)*NH + h;
            float e = __expf(g_pm[idx] - M);
            es[i] = e;
            Z += g_pz[idx] * e;
            T += g_pt[idx] * e;
        }
        float iz = 1.f / Z;
        sT = T; sInvZ = iz;
        g_Mx[b*NH + h] = M;
        g_invZ[b*NH + h] = iz;
    }
    __syncthreads();

    for (int l = t; l < NL; l += 256) {
        float A = 0.f;
        #pragma unroll
        for (int i = 0; i < SPLIT; i++)
            A += g_pa[((size_t)(b*SPLIT + i)*NH + h)*NL + l] * es[i];
        cvec[l] = lnkv_g[l] * (A - sT) * sInvZ + lnkv_b[l];
    }
    __syncthreads();

    {
        const int d = t & 63, lg = t >> 6;
        float acc = 0.f;
        const int l0 = lg * 128;
        for (int l = l0; l < l0 + 128; l++)
            acc += cvec[l] * W_v[l*NDM + h*NDK + d];
        part[lg*64 + d] = acc;
    }
    __syncthreads();
    if (t < 64) {
        float c = part[t] + part[64+t] + part[128+t] + part[192+t];
        g_ctx[b*NDM + h*NDK + t] = c;
    }
}

// =========================================================================
// Kernel 4a: context output = x_trafic @ res_W + res_b + ctx
// =========================================================================
__global__ void __launch_bounds__(512) k4_context(
    const float* __restrict__ x_trafic,
    const float* __restrict__ res_W, const float* __restrict__ res_b,
    float* __restrict__ out)
{
    __shared__ float  xt[NL];
    __shared__ float4 part4[4*128];
    const int t = threadIdx.x, b = blockIdx.x;
    xt[t] = x_trafic[b*NL + t];
    __syncthreads();

    const int og = t & 127, lg = t >> 7;
    const float4* W4 = (const float4*)res_W;
    float4 acc = {0,0,0,0};
    const int l0 = lg * 128;
    for (int l = l0; l < l0 + 128; l++) {
        float s = xt[l];
        float4 w = W4[l*128 + og];
        acc.x += s*w.x; acc.y += s*w.y; acc.z += s*w.z; acc.w += s*w.w;
    }
    part4[lg*128 + og] = acc;
    __syncthreads();
    if (t < 128) {
        float4 a = part4[t], b2 = part4[128+t], c = part4[256+t], d = part4[384+t];
        float4 rb = ((const float4*)res_b)[t];
        float4 cx = ((const float4*)g_ctx)[b*128 + t];
        float4 o;
        o.x = a.x + b2.x + c.x + d.x + rb.x + cx.x;
        o.y = a.y + b2.y + c.y + d.y + rb.y + cx.y;
        o.z = a.z + b2.z + c.z + d.z + rb.z + cx.z;
        o.w = a.w + b2.w + c.w + d.w + rb.w + cx.w;
        ((float4*)out)[b*128 + t] = o;
    }
}

// =========================================================================
// Kernel 4b: attn output = exp(score - M) * invZ
// =========================================================================
__global__ void __launch_bounds__(256) k4_attn(float* __restrict__ out)
{
    int i = blockIdx.x * 256 + threadIdx.x;   // [0, B*H*P)
    int bh = i >> 11;                          // P = 2048
    out[NB*NDM + i] = __expf(g_scores[i] - g_Mx[bh]) * g_invZ[bh];
}

// =========================================================================
extern "C" void kernel_launch(void* const* d_in, const int* in_sizes, int n_in,
                              void* d_out, int out_size)
{
    const float* x_trafic  = (const float*)d_in[0];
    const float* x_dynamic = (const float*)d_in[1];
    // d_in[2] x_known unused by the reference
    const float* W_q    = (const float*)d_in[3];
    const float* W_k    = (const float*)d_in[4];
    const float* W_v    = (const float*)d_in[5];
    const float* lnq_g  = (const float*)d_in[6];
    const float* lnq_b  = (const float*)d_in[7];
    const float* lnkv_g = (const float*)d_in[8];
    const float* lnkv_b = (const float*)d_in[9];
    const float* res_W  = (const float*)d_in[10];
    const float* res_b  = (const float*)d_in[11];
    float* out = (float*)d_out;

    const int smem2 = (2*TILE*NL + NH*NL + 2*NH*TILE + NH + 2*TILE + 5*NH) * (int)sizeof(float);
    cudaFuncSetAttribute(k2_main, cudaFuncAttributeMaxDynamicSharedMemorySize, smem2);

    k1_prep<<<NB, 512>>>(x_trafic, W_q, W_k, lnq_g, lnq_b, lnkv_g, lnkv_b);
    k2_main<<<dim3(SPLIT, NB), 512, smem2>>>(x_dynamic);
    k3_combine<<<NB*NH, 256>>>(W_v, lnkv_g, lnkv_b);
    k4_context<<<NB, 512>>>(x_trafic, res_W, res_b, out);
    k4_attn<<<(NB*NH*NP)/256, 256>>>(out);
}

// round 4
// speedup vs baseline: 1.5211x; 1.5211x over previous
#include <cuda_runtime.h>
#include <cstdint>

#define NB   64      // B
#define NP   2048    // P
#define NL   512     // L
#define NDM  512     // D_MODEL
#define NH   8       // heads
#define NDK  64
#define SPLIT 8
#define ROWS_PER_BLK (NP/SPLIT)   // 256
#define TILE 16
#define NTILES (ROWS_PER_BLK/TILE) // 16

#define NEG_INF (__int_as_float(0xff800000))

// ------------------------- scratch (static device memory) -------------------------
__device__ float g_ug[NB*NH*NL];         // (u * lnkv_g) per (b,h,l)
__device__ float g_ugs[NB*NH];           // sum_l ug
__device__ float g_ub[NB*NH];            // sum_l u * lnkv_b
__device__ float g_scores[NB*NH*NP];     // raw scores
__device__ float g_pm[NB*SPLIT*NH];      // partial max
__device__ float g_pz[NB*SPLIT*NH];      // partial Z
__device__ float g_pt[NB*SPLIT*NH];      // partial T
__device__ float g_pa[NB*SPLIT*NH*NL];   // partial A (8 MB)
__device__ float g_Mx[NB*NH];            // final max
__device__ float g_invZ[NB*NH];          // 1/Z
__device__ float g_ctx[NB*NDM];          // attention context

// ------------------------- helpers -------------------------
__device__ __forceinline__ uint32_t s2u(const void* p) {
    return (uint32_t)__cvta_generic_to_shared(p);
}
__device__ __forceinline__ void cp_async16(uint32_t s, const void* g) {
    asm volatile("cp.async.cg.shared.global [%0], [%1], 16;\n" :: "r"(s), "l"(g));
}
#define CP_COMMIT() asm volatile("cp.async.commit_group;\n")
#define CP_WAIT1()  asm volatile("cp.async.wait_group 1;\n")
#define CP_WAIT0()  asm volatile("cp.async.wait_group 0;\n")

// =========================================================================
// Kernel 1: per batch b: lnq = LN(x_trafic[b]); Q = lnq @ W_q;
//           u[h,l] = sum_d W_k[l, h*64+d] * Q[h*64+d];
//           g_ug = u * lnkv_g; g_ugs = sum ug; g_ub = sum u*lnkv_b
// =========================================================================
__global__ void __launch_bounds__(512) k1_prep(
    const float* __restrict__ x_trafic,
    const float* __restrict__ W_q, const float* __restrict__ W_k,
    const float* __restrict__ lnq_g, const float* __restrict__ lnq_b,
    const float* __restrict__ lnkv_g, const float* __restrict__ lnkv_b)
{
    __shared__ float  lnq_s[NL];
    __shared__ float4 Q_s4[NL/4];
    __shared__ float4 part4[4*128];
    __shared__ float  red1[16], red2[16];
    __shared__ float  sc_mean, sc_r;
    __shared__ float  ugs_sm[NH], ub_sm[NH];

    const int t = threadIdx.x, b = blockIdx.x;
    const int lane = t & 31, wid = t >> 5;

    if (t < NH) { ugs_sm[t] = 0.f; ub_sm[t] = 0.f; }

    // LN stats of x_trafic row
    float v = x_trafic[b*NL + t];
    float s1 = v, s2v = v*v;
    #pragma unroll
    for (int o = 16; o > 0; o >>= 1) {
        s1  += __shfl_xor_sync(~0u, s1, o);
        s2v += __shfl_xor_sync(~0u, s2v, o);
    }
    if (lane == 0) { red1[wid] = s1; red2[wid] = s2v; }
    __syncthreads();
    if (t == 0) {
        float a = 0.f, c = 0.f;
        #pragma unroll
        for (int i = 0; i < 16; i++) { a += red1[i]; c += red2[i]; }
        float mean = a * (1.f/NL);
        float var  = c * (1.f/NL) - mean*mean;
        sc_mean = mean;
        sc_r = rsqrtf(var + 1e-5f);
    }
    __syncthreads();
    lnq_s[t] = (v - sc_mean) * sc_r * lnq_g[t] + lnq_b[t];
    __syncthreads();

    // Q = lnq @ W_q : 128 output-groups x 4 l-groups
    {
        const int og = t & 127, lg = t >> 7;
        const float4* Wq4 = (const float4*)W_q;
        float4 acc = {0,0,0,0};
        const int l0 = lg * 128;
        for (int l = l0; l < l0 + 128; l++) {
            float s = lnq_s[l];
            float4 w = Wq4[l*128 + og];
            acc.x += s*w.x; acc.y += s*w.y; acc.z += s*w.z; acc.w += s*w.w;
        }
        part4[lg*128 + og] = acc;
    }
    __syncthreads();
    if (t < 128) {
        float4 a = part4[t], b2 = part4[128+t], c = part4[256+t], d = part4[384+t];
        a.x += b2.x + c.x + d.x;
        a.y += b2.y + c.y + d.y;
        a.z += b2.z + c.z + d.z;
        a.w += b2.w + c.w + d.w;
        Q_s4[t] = a;
    }
    __syncthreads();

    // u[h,l]: warp wid handles rows l = wid + 16*it; lane covers 16 contiguous cols (head = lane/4)
    const float4* Wk4 = (const float4*)W_k;
    const int h = lane >> 2;
    float ugs_p = 0.f, ub_p = 0.f;
    for (int it = 0; it < 32; it++) {
        int l = wid + 16*it;
        float acc = 0.f;
        #pragma unroll
        for (int j = 0; j < 4; j++) {
            float4 w = Wk4[l*128 + lane*4 + j];
            float4 q = Q_s4[lane*4 + j];
            acc += w.x*q.x + w.y*q.y + w.z*q.z + w.w*q.w;
        }
        acc += __shfl_xor_sync(~0u, acc, 1);
        acc += __shfl_xor_sync(~0u, acc, 2);
        if ((lane & 3) == 0) {
            float ug = acc * lnkv_g[l];
            g_ug[(b*NH + h)*NL + l] = ug;
            ugs_p += ug;
            ub_p  += acc * lnkv_b[l];
        }
    }
    if ((lane & 3) == 0) {
        atomicAdd(&ugs_sm[h], ugs_p);
        atomicAdd(&ub_sm[h], ub_p);
    }
    __syncthreads();
    if (t < NH) {
        g_ugs[b*NH + t] = ugs_sm[t];
        g_ub [b*NH + t] = ub_sm[t];
    }
}

// =========================================================================
// Kernel 2: main fused pass over x_dynamic (single HBM read).
// Per block (split, b): 256 rows in tiles of 16.
//  phase3: warp-per-row LN stats + 8 head dots -> scores
//  phase4: online softmax update per head (warp 0)
//  phase5: col-distributed accumulation A[h][l] += e'*x
// =========================================================================
__global__ void __launch_bounds__(512) k2_main(const float* __restrict__ x_dyn)
{
    extern __shared__ float sm[];
    float* buf     = sm;                     // 2*16*512
    float* ug_s    = sm + 2*TILE*NL;         // 4096
    float* sc_s    = ug_s + NH*NL;           // 128
    float* ea_s    = sc_s + NH*TILE;         // 128
    float* scale_s = ea_s + NH*TILE;         // 8
    float* mrow_s  = scale_s + NH;           // 16
    float* rrow_s  = mrow_s + TILE;          // 16
    float* mrun_s  = rrow_s + TILE;          // 8
    float* zrun_s  = mrun_s + NH;            // 8
    float* trun_s  = zrun_s + NH;            // 8
    float* ugs_s   = trun_s + NH;            // 8
    float* ub_s    = ugs_s + NH;             // 8

    const int t = threadIdx.x;
    const int split = blockIdx.x, b = blockIdx.y;
    const int lane = t & 31, wid = t >> 5;

    // load ug tile for this b (4096 floats)
    {
        const float4* gug4 = (const float4*)(g_ug + (size_t)b*NH*NL);
        float4* ug4 = (float4*)ug_s;
        ug4[t]       = gug4[t];
        ug4[t + 512] = gug4[t + 512];
    }
    if (t < NH) {
        ugs_s[t] = g_ugs[b*NH + t];
        ub_s [t] = g_ub [b*NH + t];
        mrun_s[t] = NEG_INF; zrun_s[t] = 0.f; trun_s[t] = 0.f;
    }

    const float* xbase = x_dyn + ((size_t)b*NP + (size_t)split*ROWS_PER_BLK)*NL;

    // prefetch tile 0
    {
        uint32_t dst = s2u(buf);
        const float4* src = (const float4*)xbase;
        #pragma unroll
        for (int j = 0; j < 4; j++)
            cp_async16(dst + (uint32_t)(t + 512*j)*16u, src + t + 512*j);
        CP_COMMIT();
    }

    const int hg = t >> 7, cg = t & 127;
    const int h0 = 2*hg, h1 = 2*hg + 1;
    float4 A0 = {0,0,0,0}, A1 = {0,0,0,0};
    const float4* ug4s = (const float4*)ug_s;

    __syncthreads();

    #pragma unroll 1
    for (int tile = 0; tile < NTILES; tile++) {
        float* xb = buf + (tile & 1)*TILE*NL;
        if (tile + 1 < NTILES) {
            float* nb = buf + ((tile+1) & 1)*TILE*NL;
            uint32_t dst = s2u(nb);
            const float4* src = (const float4*)(xbase + (size_t)(tile+1)*TILE*NL);
            #pragma unroll
            for (int j = 0; j < 4; j++)
                cp_async16(dst + (uint32_t)(t + 512*j)*16u, src + t + 512*j);
            CP_COMMIT();
            CP_WAIT1();
        } else {
            CP_WAIT0();
        }
        __syncthreads();

        // ---- phase 3: warp wid processes row wid ----
        {
            const float4* xr = (const float4*)(xb + wid*NL);
            float dd[8];
            float sum, sq;
            {   // heads 0..3 + stats
                float4 s4 = {0,0,0,0}, q4 = {0,0,0,0};
                float4 dv0={0,0,0,0}, dv1={0,0,0,0}, dv2={0,0,0,0}, dv3={0,0,0,0};
                #pragma unroll
                for (int i = 0; i < 4; i++) {
                    float4 v = xr[lane + 32*i];
                    s4.x += v.x; s4.y += v.y; s4.z += v.z; s4.w += v.w;
                    q4.x += v.x*v.x; q4.y += v.y*v.y; q4.z += v.z*v.z; q4.w += v.w*v.w;
                    float4 u0 = ug4s[0*128 + lane + 32*i];
                    float4 u1 = ug4s[1*128 + lane + 32*i];
                    float4 u2 = ug4s[2*128 + lane + 32*i];
                    float4 u3 = ug4s[3*128 + lane + 32*i];
                    dv0.x += v.x*u0.x; dv0.y += v.y*u0.y; dv0.z += v.z*u0.z; dv0.w += v.w*u0.w;
                    dv1.x += v.x*u1.x; dv1.y += v.y*u1.y; dv1.z += v.z*u1.z; dv1.w += v.w*u1.w;
                    dv2.x += v.x*u2.x; dv2.y += v.y*u2.y; dv2.z += v.z*u2.z; dv2.w += v.w*u2.w;
                    dv3.x += v.x*u3.x; dv3.y += v.y*u3.y; dv3.z += v.z*u3.z; dv3.w += v.w*u3.w;
                }
                dd[0] = dv0.x+dv0.y+dv0.z+dv0.w;
                dd[1] = dv1.x+dv1.y+dv1.z+dv1.w;
                dd[2] = dv2.x+dv2.y+dv2.z+dv2.w;
                dd[3] = dv3.x+dv3.y+dv3.z+dv3.w;
                sum = s4.x+s4.y+s4.z+s4.w;
                sq  = q4.x+q4.y+q4.z+q4.w;
            }
            {   // heads 4..7
                float4 dv0={0,0,0,0}, dv1={0,0,0,0}, dv2={0,0,0,0}, dv3={0,0,0,0};
                #pragma unroll
                for (int i = 0; i < 4; i++) {
                    float4 v = xr[lane + 32*i];
                    float4 u0 = ug4s[4*128 + lane + 32*i];
                    float4 u1 = ug4s[5*128 + lane + 32*i];
                    float4 u2 = ug4s[6*128 + lane + 32*i];
                    float4 u3 = ug4s[7*128 + lane + 32*i];
                    dv0.x += v.x*u0.x; dv0.y += v.y*u0.y; dv0.z += v.z*u0.z; dv0.w += v.w*u0.w;
                    dv1.x += v.x*u1.x; dv1.y += v.y*u1.y; dv1.z += v.z*u1.z; dv1.w += v.w*u1.w;
                    dv2.x += v.x*u2.x; dv2.y += v.y*u2.y; dv2.z += v.z*u2.z; dv2.w += v.w*u2.w;
                    dv3.x += v.x*u3.x; dv3.y += v.y*u3.y; dv3.z += v.z*u3.z; dv3.w += v.w*u3.w;
                }
                dd[4] = dv0.x+dv0.y+dv0.z+dv0.w;
                dd[5] = dv1.x+dv1.y+dv1.z+dv1.w;
                dd[6] = dv2.x+dv2.y+dv2.z+dv2.w;
                dd[7] = dv3.x+dv3.y+dv3.z+dv3.w;
            }
            #pragma unroll
            for (int o = 16; o > 0; o >>= 1) {
                sum += __shfl_xor_sync(~0u, sum, o);
                sq  += __shfl_xor_sync(~0u, sq,  o);
                #pragma unroll
                for (int k = 0; k < 8; k++) dd[k] += __shfl_xor_sync(~0u, dd[k], o);
            }
            float mean = sum * (1.f/NL);
            float var  = sq  * (1.f/NL) - mean*mean;
            float r = rsqrtf(var + 1e-5f);
            if (lane == 0) { mrow_s[wid] = mean; rrow_s[wid] = r; }
            if (lane < NH) {
                float dsel = dd[0];
                #pragma unroll
                for (int k = 1; k < 8; k++) if (lane == k) dsel = dd[k];
                float s = (r * (dsel - mean * ugs_s[lane]) + ub_s[lane]) * 0.125f;
                sc_s[lane*TILE + wid] = s;
                g_scores[((size_t)(b*NH + lane))*NP + split*ROWS_PER_BLK + tile*TILE + wid] = s;
            }
        }
        __syncthreads();

        // ---- phase 4: online softmax update (threads 0..7, one per head) ----
        if (t < NH) {
            const int h = t;
            float mr = mrun_s[h];
            float tmax = NEG_INF;
            #pragma unroll
            for (int p = 0; p < TILE; p++) tmax = fmaxf(tmax, sc_s[h*TILE + p]);
            float mn = fmaxf(mr, tmax);
            float scale = __expf(mr - mn);
            float zadd = 0.f, tadd = 0.f;
            #pragma unroll
            for (int p = 0; p < TILE; p++) {
                float e  = __expf(sc_s[h*TILE + p] - mn);
                float ea = e * rrow_s[p];
                ea_s[h*TILE + p] = ea;
                zadd += e;
                tadd += ea * mrow_s[p];
            }
            zrun_s[h] = zrun_s[h]*scale + zadd;
            trun_s[h] = trun_s[h]*scale + tadd;
            mrun_s[h] = mn;
            scale_s[h] = scale;
        }
        __syncthreads();

        // ---- phase 5: accumulate A (thread owns 4 cols x 2 heads) ----
        {
            float sc0 = scale_s[h0], sc1 = scale_s[h1];
            A0.x *= sc0; A0.y *= sc0; A0.z *= sc0; A0.w *= sc0;
            A1.x *= sc1; A1.y *= sc1; A1.z *= sc1; A1.w *= sc1;
            const float4* xc = (const float4*)xb;
            #pragma unroll
            for (int p = 0; p < TILE; p++) {
                float4 v = xc[p*128 + cg];
                float e0 = ea_s[h0*TILE + p];
                float e1 = ea_s[h1*TILE + p];
                A0.x += e0*v.x; A0.y += e0*v.y; A0.z += e0*v.z; A0.w += e0*v.w;
                A1.x += e1*v.x; A1.y += e1*v.y; A1.z += e1*v.z; A1.w += e1*v.w;
            }
        }
        __syncthreads();
    }

    // epilogue: write partials
    {
        float* pa = g_pa + (size_t)(b*SPLIT + split)*NH*NL;
        ((float4*)(pa + h0*NL))[cg] = A0;
        ((float4*)(pa + h1*NL))[cg] = A1;
    }
    if (t < NH) {
        int idx = (b*SPLIT + split)*NH + t;
        g_pm[idx] = mrun_s[t];
        g_pz[idx] = zrun_s[t];
        g_pt[idx] = trun_s[t];
    }
}

// =========================================================================
// Kernel 3: combine split partials per (b,h); project through W_v -> ctx
// =========================================================================
__global__ void __launch_bounds__(256) k3_combine(
    const float* __restrict__ W_v,
    const float* __restrict__ lnkv_g, const float* __restrict__ lnkv_b)
{
    __shared__ float es[SPLIT];
    __shared__ float sT, sInvZ;
    __shared__ float cvec[NL];
    __shared__ float part[4*64];

    const int t = threadIdx.x;
    const int b = blockIdx.x >> 3, h = blockIdx.x & 7;

    if (t == 0) {
        float M = NEG_INF;
        #pragma unroll
        for (int i = 0; i < SPLIT; i++)
            M = fmaxf(M, g_pm[(b*SPLIT + i)*NH + h]);
        float Z = 0.f, T = 0.f;
        #pragma unroll
        for (int i = 0; i < SPLIT; i++) {
            int idx = (b*SPLIT + i)*NH + h;
            float e = __expf(g_pm[idx] - M);
            es[i] = e;
            Z += g_pz[idx] * e;
            T += g_pt[idx] * e;
        }
        float iz = 1.f / Z;
        sT = T; sInvZ = iz;
        g_Mx[b*NH + h] = M;
        g_invZ[b*NH + h] = iz;
    }
    __syncthreads();

    for (int l = t; l < NL; l += 256) {
        float A = 0.f;
        #pragma unroll
        for (int i = 0; i < SPLIT; i++)
            A += g_pa[((size_t)(b*SPLIT + i)*NH + h)*NL + l] * es[i];
        cvec[l] = lnkv_g[l] * (A - sT) * sInvZ + lnkv_b[l];
    }
    __syncthreads();

    {
        const int d = t & 63, lg = t >> 6;
        float acc = 0.f;
        const int l0 = lg * 128;
        for (int l = l0; l < l0 + 128; l++)
            acc += cvec[l] * W_v[l*NDM + h*NDK + d];
        part[lg*64 + d] = acc;
    }
    __syncthreads();
    if (t < 64) {
        float c = part[t] + part[64+t] + part[128+t] + part[192+t];
        g_ctx[b*NDM + h*NDK + t] = c;
    }
}

// =========================================================================
// Kernel 4a: context output = x_trafic @ res_W + res_b + ctx
// =========================================================================
__global__ void __launch_bounds__(512) k4_context(
    const float* __restrict__ x_trafic,
    const float* __restrict__ res_W, const float* __restrict__ res_b,
    float* __restrict__ out)
{
    __shared__ float  xt[NL];
    __shared__ float4 part4[4*128];
    const int t = threadIdx.x, b = blockIdx.x;
    xt[t] = x_trafic[b*NL + t];
    __syncthreads();

    const int og = t & 127, lg = t >> 7;
    const float4* W4 = (const float4*)res_W;
    float4 acc = {0,0,0,0};
    const int l0 = lg * 128;
    for (int l = l0; l < l0 + 128; l++) {
        float s = xt[l];
        float4 w = W4[l*128 + og];
        acc.x += s*w.x; acc.y += s*w.y; acc.z += s*w.z; acc.w += s*w.w;
    }
    part4[lg*128 + og] = acc;
    __syncthreads();
    if (t < 128) {
        float4 a = part4[t], b2 = part4[128+t], c = part4[256+t], d = part4[384+t];
        float4 rb = ((const float4*)res_b)[t];
        float4 cx = ((const float4*)g_ctx)[b*128 + t];
        float4 o;
        o.x = a.x + b2.x + c.x + d.x + rb.x + cx.x;
        o.y = a.y + b2.y + c.y + d.y + rb.y + cx.y;
        o.z = a.z + b2.z + c.z + d.z + rb.z + cx.z;
        o.w = a.w + b2.w + c.w + d.w + rb.w + cx.w;
        ((float4*)out)[b*128 + t] = o;
    }
}

// =========================================================================
// Kernel 4b: attn output = exp(score - M) * invZ
// =========================================================================
__global__ void __launch_bounds__(256) k4_attn(float* __restrict__ out)
{
    int i = blockIdx.x * 256 + threadIdx.x;   // [0, B*H*P)
    int bh = i >> 11;                          // P = 2048
    out[NB*NDM + i] = __expf(g_scores[i] - g_Mx[bh]) * g_invZ[bh];
}

// =========================================================================
extern "C" void kernel_launch(void* const* d_in, const int* in_sizes, int n_in,
                              void* d_out, int out_size)
{
    const float* x_trafic  = (const float*)d_in[0];
    const float* x_dynamic = (const float*)d_in[1];
    // d_in[2] x_known unused by the reference
    const float* W_q    = (const float*)d_in[3];
    const float* W_k    = (const float*)d_in[4];
    const float* W_v    = (const float*)d_in[5];
    const float* lnq_g  = (const float*)d_in[6];
    const float* lnq_b  = (const float*)d_in[7];
    const float* lnkv_g = (const float*)d_in[8];
    const float* lnkv_b = (const float*)d_in[9];
    const float* res_W  = (const float*)d_in[10];
    const float* res_b  = (const float*)d_in[11];
    float* out = (float*)d_out;

    const int smem2 = (2*TILE*NL + NH*NL + 2*NH*TILE + NH + 2*TILE + 5*NH) * (int)sizeof(float);
    cudaFuncSetAttribute(k2_main, cudaFuncAttributeMaxDynamicSharedMemorySize, smem2);

    k1_prep<<<NB, 512>>>(x_trafic, W_q, W_k, lnq_g, lnq_b, lnkv_g, lnkv_b);
    k2_main<<<dim3(SPLIT, NB), 512, smem2>>>(x_dynamic);
    k3_combine<<<NB*NH, 256>>>(W_v, lnkv_g, lnkv_b);
    k4_context<<<NB, 512>>>(x_trafic, res_W, res_b, out);
    k4_attn<<<(NB*NH*NP)/256, 256>>>(out);
}

// round 6
// speedup vs baseline: 2.1071x; 1.3853x over previous
#include <cuda_runtime.h>
#include <cstdint>

#define NB   64      // B
#define NP   2048    // P
#define NL   512     // L
#define NDM  512     // D_MODEL
#define NH   8       // heads
#define NDK  64
#define SPLIT 2
#define ROWS_PER_BLK (NP/SPLIT)    // 1024
#define TILE 32
#define NTILES (ROWS_PER_BLK/TILE) // 32

#define NEG_INF (__int_as_float(0xff800000))

// ------------------------- scratch (static device memory) -------------------------
__device__ float g_ug[NB*NH*NL];         // (u * lnkv_g) per (b,h,l)
__device__ float g_ugs[NB*NH];           // sum_l ug
__device__ float g_ub[NB*NH];            // sum_l u * lnkv_b
__device__ float g_scores[NB*NH*NP];     // raw scores
__device__ float g_pm[NB*SPLIT*NH];      // partial max
__device__ float g_pz[NB*SPLIT*NH];      // partial Z
__device__ float g_pt[NB*SPLIT*NH];      // partial T
__device__ float g_pa[NB*SPLIT*NH*NL];   // partial A (2 MB)
__device__ float g_Mx[NB*NH];            // final max
__device__ float g_invZ[NB*NH];          // 1/Z
__device__ float g_res[NB*NDM];          // residual = x_trafic @ res_W + res_b

// ------------------------- helpers -------------------------
__device__ __forceinline__ uint32_t s2u(const void* p) {
    return (uint32_t)__cvta_generic_to_shared(p);
}
__device__ __forceinline__ void cp_async16(uint32_t s, const void* g) {
    asm volatile("cp.async.cg.shared.global [%0], [%1], 16;\n" :: "r"(s), "l"(g));
}
#define CP_COMMIT() asm volatile("cp.async.commit_group;\n")
#define CP_WAIT1()  asm volatile("cp.async.wait_group 1;\n")
#define CP_WAIT0()  asm volatile("cp.async.wait_group 0;\n")

// =========================================================================
// Kernel 1: blocks 0..63   : per batch b: Q/u prep -> g_ug, g_ugs, g_ub
//           blocks 64..127 : residual GEMV -> g_res
// =========================================================================
__global__ void __launch_bounds__(512) k1_prep(
    const float* __restrict__ x_trafic,
    const float* __restrict__ W_q, const float* __restrict__ W_k,
    const float* __restrict__ lnq_g, const float* __restrict__ lnq_b,
    const float* __restrict__ lnkv_g, const float* __restrict__ lnkv_b,
    const float* __restrict__ res_W, const float* __restrict__ res_b)
{
    __shared__ float  lnq_s[NL];
    __shared__ float4 Q_s4[NL/4];
    __shared__ float4 part4[4*128];
    __shared__ float  red1[16], red2[16];
    __shared__ float  sc_mean, sc_r;
    __shared__ float  ugs_sm[NH], ub_sm[NH];

    const int t = threadIdx.x;
    const int lane = t & 31, wid = t >> 5;

    if (blockIdx.x >= NB) {
        // ---------------- residual GEMV: g_res[b] = x_t[b] @ res_W + res_b -------
        const int b = blockIdx.x - NB;
        lnq_s[t] = x_trafic[b*NL + t];
        __syncthreads();
        const int og = t & 127, lg = t >> 7;
        const float4* W4 = (const float4*)res_W;
        float4 acc = {0,0,0,0};
        const int l0 = lg * 128;
        #pragma unroll 4
        for (int l = l0; l < l0 + 128; l++) {
            float s = lnq_s[l];
            float4 w = W4[l*128 + og];
            acc.x += s*w.x; acc.y += s*w.y; acc.z += s*w.z; acc.w += s*w.w;
        }
        part4[lg*128 + og] = acc;
        __syncthreads();
        if (t < 128) {
            float4 a = part4[t], b2 = part4[128+t], c = part4[256+t], d = part4[384+t];
            float4 rb = ((const float4*)res_b)[t];
            float4 o;
            o.x = a.x + b2.x + c.x + d.x + rb.x;
            o.y = a.y + b2.y + c.y + d.y + rb.y;
            o.z = a.z + b2.z + c.z + d.z + rb.z;
            o.w = a.w + b2.w + c.w + d.w + rb.w;
            ((float4*)g_res)[b*128 + t] = o;
        }
        return;
    }

    const int b = blockIdx.x;
    if (t < NH) { ugs_sm[t] = 0.f; ub_sm[t] = 0.f; }

    // LN stats of x_trafic row
    float v = x_trafic[b*NL + t];
    float s1 = v, s2v = v*v;
    #pragma unroll
    for (int o = 16; o > 0; o >>= 1) {
        s1  += __shfl_xor_sync(~0u, s1, o);
        s2v += __shfl_xor_sync(~0u, s2v, o);
    }
    if (lane == 0) { red1[wid] = s1; red2[wid] = s2v; }
    __syncthreads();
    if (t == 0) {
        float a = 0.f, c = 0.f;
        #pragma unroll
        for (int i = 0; i < 16; i++) { a += red1[i]; c += red2[i]; }
        float mean = a * (1.f/NL);
        float var  = c * (1.f/NL) - mean*mean;
        sc_mean = mean;
        sc_r = rsqrtf(var + 1e-5f);
    }
    __syncthreads();
    lnq_s[t] = (v - sc_mean) * sc_r * lnq_g[t] + lnq_b[t];
    __syncthreads();

    // Q = lnq @ W_q
    {
        const int og = t & 127, lg = t >> 7;
        const float4* Wq4 = (const float4*)W_q;
        float4 acc = {0,0,0,0};
        const int l0 = lg * 128;
        #pragma unroll 4
        for (int l = l0; l < l0 + 128; l++) {
            float s = lnq_s[l];
            float4 w = Wq4[l*128 + og];
            acc.x += s*w.x; acc.y += s*w.y; acc.z += s*w.z; acc.w += s*w.w;
        }
        part4[lg*128 + og] = acc;
    }
    __syncthreads();
    if (t < 128) {
        float4 a = part4[t], b2 = part4[128+t], c = part4[256+t], d = part4[384+t];
        a.x += b2.x + c.x + d.x;
        a.y += b2.y + c.y + d.y;
        a.z += b2.z + c.z + d.z;
        a.w += b2.w + c.w + d.w;
        Q_s4[t] = a;
    }
    __syncthreads();

    // u[h,l]
    const float4* Wk4 = (const float4*)W_k;
    const int h = lane >> 2;
    float ugs_p = 0.f, ub_p = 0.f;
    for (int it = 0; it < 32; it++) {
        int l = wid + 16*it;
        float acc = 0.f;
        #pragma unroll
        for (int j = 0; j < 4; j++) {
            float4 w = Wk4[l*128 + lane*4 + j];
            float4 q = Q_s4[lane*4 + j];
            acc += w.x*q.x + w.y*q.y + w.z*q.z + w.w*q.w;
        }
        acc += __shfl_xor_sync(~0u, acc, 1);
        acc += __shfl_xor_sync(~0u, acc, 2);
        if ((lane & 3) == 0) {
            float ug = acc * lnkv_g[l];
            g_ug[(b*NH + h)*NL + l] = ug;
            ugs_p += ug;
            ub_p  += acc * lnkv_b[l];
        }
    }
    if ((lane & 3) == 0) {
        atomicAdd(&ugs_sm[h], ugs_p);
        atomicAdd(&ub_sm[h], ub_p);
    }
    __syncthreads();
    if (t < NH) {
        g_ugs[b*NH + t] = ugs_sm[t];
        g_ub [b*NH + t] = ub_sm[t];
    }
}

// =========================================================================
// Kernel 2: main fused pass over x_dynamic.
//  TILE=32 rows/iter, double-buffered cp.async.
//  phase3: 8 warps x 4 rows, register-blocked ug, butterfly reduce
//  phase4: 1 warp per head, 32 lanes over p
//  phase5: thread = (col4-group, 4-head group, p-half)
// =========================================================================
__global__ void __launch_bounds__(512, 1) k2_main(const float* __restrict__ x_dyn)
{
    extern __shared__ float sm[];
    float* buf     = sm;                     // 2*32*512 = 32768
    float* ug_s    = sm + 2*TILE*NL;         // 4096
    float* sc_s    = ug_s + NH*NL;           // 256 [h][p]
    float* ea_s    = sc_s + NH*TILE;         // 256 [h][p]
    float* scale_s = ea_s + NH*TILE;         // 8
    float* mrow_s  = scale_s + NH;           // 32
    float* rrow_s  = mrow_s + TILE;          // 32
    float* mrun_s  = rrow_s + TILE;          // 8
    float* zrun_s  = mrun_s + NH;            // 8
    float* trun_s  = zrun_s + NH;            // 8
    float* ugs_s   = trun_s + NH;            // 8
    float* ub_s    = ugs_s + NH;             // 8

    const int t = threadIdx.x;
    const int split = blockIdx.x, b = blockIdx.y;
    const int lane = t & 31, wid = t >> 5;

    // load ug for this b (4096 floats)
    {
        const float4* gug4 = (const float4*)(g_ug + (size_t)b*NH*NL);
        float4* ug4 = (float4*)ug_s;
        ug4[t]       = gug4[t];
        ug4[t + 512] = gug4[t + 512];
    }
    if (t < NH) {
        ugs_s[t] = g_ugs[b*NH + t];
        ub_s [t] = g_ub [b*NH + t];
        mrun_s[t] = NEG_INF; zrun_s[t] = 0.f; trun_s[t] = 0.f;
    }

    const float* xbase = x_dyn + ((size_t)b*NP + (size_t)split*ROWS_PER_BLK)*NL;

    // prefetch tile 0 (32*512 floats = 4096 float4; 8 per thread)
    {
        uint32_t dst = s2u(buf);
        const float4* src = (const float4*)xbase;
        #pragma unroll
        for (int j = 0; j < 8; j++)
            cp_async16(dst + (uint32_t)(t + 512*j)*16u, src + t + 512*j);
        CP_COMMIT();
    }

    // phase5 thread mapping
    const int cg = t & 127;           // float4 column group
    const int hg = (t >> 7) & 1;      // head group: heads hg*4..hg*4+3
    const int pg = t >> 8;            // p half: [pg*16, pg*16+16)
    float4 A[4] = {{0,0,0,0},{0,0,0,0},{0,0,0,0},{0,0,0,0}};
    const float4* ug4s = (const float4*)ug_s;

    #pragma unroll 1
    for (int tile = 0; tile < NTILES; tile++) {
        float* xb = buf + (tile & 1)*TILE*NL;

        __syncthreads();   // prev phase5 done: safe to refill other buffer / rewrite ea_s

        if (tile + 1 < NTILES) {
            float* nb = buf + ((tile+1) & 1)*TILE*NL;
            uint32_t dst = s2u(nb);
            const float4* src = (const float4*)(xbase + (size_t)(tile+1)*TILE*NL);
            #pragma unroll
            for (int j = 0; j < 8; j++)
                cp_async16(dst + (uint32_t)(t + 512*j)*16u, src + t + 512*j);
            CP_COMMIT();
            CP_WAIT1();
        } else {
            CP_WAIT0();
        }
        __syncthreads();   // tile data visible

        // ---- phase 3: warps 0..7, warp w handles rows w*4..w*4+3 ----
        if (wid < 8) {
            const float4* xw = (const float4*)xb + (wid*4)*128;
            float dd[32];
            #pragma unroll
            for (int i = 0; i < 32; i++) dd[i] = 0.f;
            float st[8] = {0,0,0,0,0,0,0,0};

            // pass A: heads 0..3 + stats
            #pragma unroll
            for (int i = 0; i < 4; i++) {
                const int idx = lane + 32*i;
                float4 u0 = ug4s[0*128+idx], u1 = ug4s[1*128+idx];
                float4 u2 = ug4s[2*128+idx], u3 = ug4s[3*128+idx];
                #pragma unroll
                for (int r = 0; r < 4; r++) {
                    float4 v = xw[r*128 + idx];
                    st[r]   += v.x + v.y + v.z + v.w;
                    st[4+r] += v.x*v.x + v.y*v.y + v.z*v.z + v.w*v.w;
                    dd[r*8+0] += v.x*u0.x + v.y*u0.y + v.z*u0.z + v.w*u0.w;
                    dd[r*8+1] += v.x*u1.x + v.y*u1.y + v.z*u1.z + v.w*u1.w;
                    dd[r*8+2] += v.x*u2.x + v.y*u2.y + v.z*u2.z + v.w*u2.w;
                    dd[r*8+3] += v.x*u3.x + v.y*u3.y + v.z*u3.z + v.w*u3.w;
                }
            }
            // pass B: heads 4..7
            #pragma unroll
            for (int i = 0; i < 4; i++) {
                const int idx = lane + 32*i;
                float4 u0 = ug4s[4*128+idx], u1 = ug4s[5*128+idx];
                float4 u2 = ug4s[6*128+idx], u3 = ug4s[7*128+idx];
                #pragma unroll
                for (int r = 0; r < 4; r++) {
                    float4 v = xw[r*128 + idx];
                    dd[r*8+4] += v.x*u0.x + v.y*u0.y + v.z*u0.z + v.w*u0.w;
                    dd[r*8+5] += v.x*u1.x + v.y*u1.y + v.z*u1.z + v.w*u1.w;
                    dd[r*8+6] += v.x*u2.x + v.y*u2.y + v.z*u2.z + v.w*u2.w;
                    dd[r*8+7] += v.x*u3.x + v.y*u3.y + v.z*u3.z + v.w*u3.w;
                }
            }

            // butterfly multi-value reduce: lane k ends with sum of dd[k]
            #pragma unroll
            for (int o = 16; o >= 1; o >>= 1) {
                #pragma unroll
                for (int i = 0; i < o; i++) {
                    bool hi = (lane & o) != 0;
                    float mine   = hi ? dd[i+o] : dd[i];
                    float theirs = hi ? dd[i]   : dd[i+o];
                    dd[i] = mine + __shfl_xor_sync(0xffffffffu, theirs, o);
                }
            }
            // stats: lane k ends with st[k&7]
            #pragma unroll
            for (int o = 16; o >= 8; o >>= 1) {
                #pragma unroll
                for (int i = 0; i < 8; i++)
                    st[i] += __shfl_xor_sync(0xffffffffu, st[i], o);
            }
            #pragma unroll
            for (int o = 4; o >= 1; o >>= 1) {
                #pragma unroll
                for (int i = 0; i < o; i++) {
                    bool hi = (lane & o) != 0;
                    float mine   = hi ? st[i+o] : st[i];
                    float theirs = hi ? st[i]   : st[i+o];
                    st[i] = mine + __shfl_xor_sync(0xffffffffu, theirs, o);
                }
            }

            const int r = lane >> 3, h = lane & 7;
            float sfin = st[0];
            float mean = __shfl_sync(0xffffffffu, sfin, r) * (1.f/NL);
            float sqv  = __shfl_sync(0xffffffffu, sfin, r + 4) * (1.f/NL);
            float var  = sqv - mean*mean;
            float rs   = rsqrtf(var + 1e-5f);
            float s = (rs * (dd[0] - mean * ugs_s[h]) + ub_s[h]) * 0.125f;
            const int prow = wid*4 + r;
            sc_s[h*TILE + prow] = s;
            if (h == 0) { mrow_s[prow] = mean; rrow_s[prow] = rs; }
        }
        __syncthreads();

        // ---- phase 4: warp w = head w, lanes over p ----
        if (wid < 8) {
            const int h = wid, p = lane;
            float s = sc_s[h*TILE + p];
            float mr = mrun_s[h];
            float tmax = s;
            #pragma unroll
            for (int o = 16; o > 0; o >>= 1)
                tmax = fmaxf(tmax, __shfl_xor_sync(~0u, tmax, o));
            float mn = fmaxf(mr, tmax);
            float e  = __expf(s - mn);
            float ea = e * rrow_s[p];
            float z = e, tt = ea * mrow_s[p];
            #pragma unroll
            for (int o = 16; o > 0; o >>= 1) {
                z  += __shfl_xor_sync(~0u, z,  o);
                tt += __shfl_xor_sync(~0u, tt, o);
            }
            ea_s[h*TILE + p] = ea;
            g_scores[((size_t)(b*NH + h))*NP + split*ROWS_PER_BLK + tile*TILE + p] = s;
            if (lane == 0) {
                float scale = __expf(mr - mn);
                zrun_s[h] = zrun_s[h]*scale + z;
                trun_s[h] = trun_s[h]*scale + tt;
                mrun_s[h] = mn;
                scale_s[h] = scale;
            }
        }
        __syncthreads();

        // ---- phase 5: accumulate A ----
        {
            float s0 = scale_s[hg*4+0], s1 = scale_s[hg*4+1];
            float s2 = scale_s[hg*4+2], s3 = scale_s[hg*4+3];
            A[0].x *= s0; A[0].y *= s0; A[0].z *= s0; A[0].w *= s0;
            A[1].x *= s1; A[1].y *= s1; A[1].z *= s1; A[1].w *= s1;
            A[2].x *= s2; A[2].y *= s2; A[2].z *= s2; A[2].w *= s2;
            A[3].x *= s3; A[3].y *= s3; A[3].z *= s3; A[3].w *= s3;
            const float4* xc = (const float4*)xb;
            #pragma unroll
            for (int pp = 0; pp < 16; pp++) {
                const int p = pg*16 + pp;
                float4 v = xc[p*128 + cg];
                float e0 = ea_s[(hg*4+0)*TILE + p];
                float e1 = ea_s[(hg*4+1)*TILE + p];
                float e2 = ea_s[(hg*4+2)*TILE + p];
                float e3 = ea_s[(hg*4+3)*TILE + p];
                A[0].x += e0*v.x; A[0].y += e0*v.y; A[0].z += e0*v.z; A[0].w += e0*v.w;
                A[1].x += e1*v.x; A[1].y += e1*v.y; A[1].z += e1*v.z; A[1].w += e1*v.w;
                A[2].x += e2*v.x; A[2].y += e2*v.y; A[2].z += e2*v.z; A[2].w += e2*v.w;
                A[3].x += e3*v.x; A[3].y += e3*v.y; A[3].z += e3*v.z; A[3].w += e3*v.w;
            }
        }
    }

    // epilogue: combine the two p-halves via smem (ug_s no longer needed)
    __syncthreads();
    if (pg == 1) {
        float4* tmp = (float4*)ug_s;
        #pragma unroll
        for (int j = 0; j < 4; j++) tmp[(hg*4+j)*128 + cg] = A[j];
    }
    __syncthreads();
    if (pg == 0) {
        const float4* tmp = (const float4*)ug_s;
        float4* pa = (float4*)(g_pa + (size_t)(b*SPLIT + split)*NH*NL);
        #pragma unroll
        for (int j = 0; j < 4; j++) {
            float4 o = tmp[(hg*4+j)*128 + cg];
            o.x += A[j].x; o.y += A[j].y; o.z += A[j].z; o.w += A[j].w;
            pa[(hg*4+j)*128 + cg] = o;
        }
    }
    if (t < NH) {
        int idx = (b*SPLIT + split)*NH + t;
        g_pm[idx] = mrun_s[t];
        g_pz[idx] = zrun_s[t];
        g_pt[idx] = trun_s[t];
    }
}

// =========================================================================
// Kernel 3: combine split partials per (b,h); project through W_v;
//           write out = residual + ctx
// =========================================================================
__global__ void __launch_bounds__(256) k3_combine(
    const float* __restrict__ W_v,
    const float* __restrict__ lnkv_g, const float* __restrict__ lnkv_b,
    float* __restrict__ out)
{
    __shared__ float es[SPLIT];
    __shared__ float sT, sInvZ;
    __shared__ float cvec[NL];
    __shared__ float part[4*64];

    const int t = threadIdx.x;
    const int b = blockIdx.x >> 3, h = blockIdx.x & 7;

    if (t == 0) {
        float M = NEG_INF;
        #pragma unroll
        for (int i = 0; i < SPLIT; i++)
            M = fmaxf(M, g_pm[(b*SPLIT + i)*NH + h]);
        float Z = 0.f, T = 0.f;
        #pragma unroll
        for (int i = 0; i < SPLIT; i++) {
            int idx = (b*SPLIT + i)*NH + h;
            float e = __expf(g_pm[idx] - M);
            es[i] = e;
            Z += g_pz[idx] * e;
            T += g_pt[idx] * e;
        }
        float iz = 1.f / Z;
        sT = T; sInvZ = iz;
        g_Mx[b*NH + h] = M;
        g_invZ[b*NH + h] = iz;
    }
    __syncthreads();

    for (int l = t; l < NL; l += 256) {
        float A = 0.f;
        #pragma unroll
        for (int i = 0; i < SPLIT; i++)
            A += g_pa[((size_t)(b*SPLIT + i)*NH + h)*NL + l] * es[i];
        cvec[l] = lnkv_g[l] * (A - sT) * sInvZ + lnkv_b[l];
    }
    __syncthreads();

    {
        const int d = t & 63, lg = t >> 6;
        float acc = 0.f;
        const int l0 = lg * 128;
        #pragma unroll 4
        for (int l = l0; l < l0 + 128; l++)
            acc += cvec[l] * W_v[l*NDM + h*NDK + d];
        part[lg*64 + d] = acc;
    }
    __syncthreads();
    if (t < 64) {
        float c = part[t] + part[64+t] + part[128+t] + part[192+t];
        out[b*NDM + h*NDK + t] = c + g_res[b*NDM + h*NDK + t];
    }
}

// =========================================================================
// Kernel 4: attn output = exp(score - M) * invZ
// =========================================================================
__global__ void __launch_bounds__(256) k4_attn(float* __restrict__ out)
{
    int i = blockIdx.x * 256 + threadIdx.x;   // [0, B*H*P)
    int bh = i >> 11;                          // P = 2048
    out[NB*NDM + i] = __expf(g_scores[i] - g_Mx[bh]) * g_invZ[bh];
}

// =========================================================================
extern "C" void kernel_launch(void* const* d_in, const int* in_sizes, int n_in,
                              void* d_out, int out_size)
{
    const float* x_trafic  = (const float*)d_in[0];
    const float* x_dynamic = (const float*)d_in[1];
    // d_in[2] x_known unused by the reference
    const float* W_q    = (const float*)d_in[3];
    const float* W_k    = (const float*)d_in[4];
    const float* W_v    = (const float*)d_in[5];
    const float* lnq_g  = (const float*)d_in[6];
    const float* lnq_b  = (const float*)d_in[7];
    const float* lnkv_g = (const float*)d_in[8];
    const float* lnkv_b = (const float*)d_in[9];
    const float* res_W  = (const float*)d_in[10];
    const float* res_b  = (const float*)d_in[11];
    float* out = (float*)d_out;

    const int smem2 = (2*TILE*NL + NH*NL + 2*NH*TILE + NH + 2*TILE + 5*NH) * (int)sizeof(float);
    cudaFuncSetAttribute(k2_main, cudaFuncAttributeMaxDynamicSharedMemorySize, smem2);

    k1_prep<<<2*NB, 512>>>(x_trafic, W_q, W_k, lnq_g, lnq_b, lnkv_g, lnkv_b, res_W, res_b);
    k2_main<<<dim3(SPLIT, NB), 512, smem2>>>(x_dynamic);
    k3_combine<<<NB*NH, 256>>>(W_v, lnkv_g, lnkv_b, out);
    k4_attn<<<(NB*NH*NP)/256, 256>>>(out);
}